// round 9
// baseline (speedup 1.0000x reference)
#include <cuda_runtime.h>
#include <cuda_fp16.h>
#include <cstdint>

#define N        8192
#define D        192
#define BM       128
#define NB       64
#define NTILES   2080             // NB*(NB+1)/2
#define TILE_BYTES (BM * D * 2)   // 49152
#define NCTA     296              // 148 SM x 2 (all co-resident: barrier-safe)
#define QW       7                // NTILES / NCTA
#define REMW     8                // NTILES - NCTA*QW
#define CHUNKS   256              // 8192 rows / 32
#define STAGGER  2700             // ~half a tile (MMA+EPI)/2 in cycles

// ---------------- device globals (zero-initialized at load) ----------------
__device__ double g_loss;
__device__ float  g_colacc[8][D];       // 8 replicated column-sum planes
__device__ float  g_sqacc[8];           // 8 replicated sum-of-squares cells
__device__ int    g_pcount;
__device__ int    g_ready;
__device__ int    g_mcount;
__device__ float  g_sq[N];
__device__ float  g_c2;                 // log2(e)/(16*bw)
__device__ uint4  g_xh[N * D * 2 / 16]; // fp16 x, row stride 384B, 16B-group XOR swizzle

// ---------------- helpers ----------------
__device__ __forceinline__ uint32_t smem_u32(const void* p) {
    uint32_t a;
    asm("{ .reg .u64 t; cvta.to.shared.u64 t, %1; cvt.u32.u64 %0, t; }" : "=r"(a) : "l"(p));
    return a;
}
#define MBAR_INIT(a, c) asm volatile("mbarrier.init.shared.b64 [%0], %1;" :: "r"(a), "r"(c) : "memory")
#define MBAR_EXPECT_TX(a, b) asm volatile("mbarrier.arrive.expect_tx.shared.b64 _, [%0], %1;" :: "r"(a), "r"(b) : "memory")
#define MBAR_WAIT(a, ph) do { \
    uint32_t _m = (a), _p = (ph), _d; \
    asm volatile("{ .reg .pred p; mbarrier.try_wait.parity.acquire.cta.shared::cta.b64 p, [%1], %2; selp.b32 %0,1,0,p; }" \
        : "=r"(_d) : "r"(_m), "r"(_p) : "memory"); \
    if (!_d) { asm volatile("{ .reg .pred P1; WL_%=: mbarrier.try_wait.parity.acquire.cta.shared::cta.b64 P1, [%0], %1, 0x989680; @P1 bra.uni WD_%=; bra.uni WL_%=; WD_%=: }" \
        :: "r"(_m), "r"(_p) : "memory"); } } while (0)
__device__ __forceinline__ void bulk_g2s(uint32_t dst, const void* src, uint32_t bytes, uint32_t mbar) {
    asm volatile("cp.async.bulk.shared::cluster.global.mbarrier::complete_tx::bytes [%0], [%1], %2, [%3];"
        :: "r"(dst), "l"(src), "r"(bytes), "r"(mbar) : "memory");
}
#define LDSM_X4(r0, r1, r2, r3, a) \
    asm volatile("ldmatrix.sync.aligned.m8n8.x4.shared.b16 {%0,%1,%2,%3}, [%4];" \
        : "=r"(r0), "=r"(r1), "=r"(r2), "=r"(r3) : "r"(a))
#define MMA16816H(d, a, b0, b1) \
    asm volatile("mma.sync.aligned.m16n8k16.row.col.f16.f16.f16.f16 " \
        "{%0,%1},{%2,%3,%4,%5},{%6,%7},{%0,%1};" \
        : "+r"((d)[0]), "+r"((d)[1]) \
        : "r"((a)[0]), "r"((a)[1]), "r"((a)[2]), "r"((a)[3]), "r"(b0), "r"(b1))
__device__ __forceinline__ float ex2f(float x) {
    float r; asm("ex2.approx.ftz.f32 %0, %1;" : "=f"(r) : "f"(x)); return r;
}

// ---------------- fused persistent kernel ----------------
#define OFF_A    0
#define OFF_B    49152
#define OFF_MBAR 98304
#define OFF_RED  98320
#define SMEM_DYN (98304 + 64 + 1024)

__global__ __launch_bounds__(256, 2) void k_all(const float* __restrict__ x,
                                                float* __restrict__ out) {
    extern __shared__ char dsm[];
    uint32_t sb = (smem_u32(dsm) + 1023u) & ~1023u;
    char* sp = dsm + (sb - smem_u32(dsm));

    int tid  = threadIdx.x;
    int wid  = tid >> 5, lane = tid & 31;
    int wM   = wid >> 2, wN = wid & 3;
    int gID  = lane >> 2, tig = lane & 3;
    int c    = blockIdx.x;

    __shared__ int s_go, s_win;

    // ================= phase 1: convert + reductions (CTAs 0..255) =================
    if (c < CHUNKS) {
        float* s_stage = (float*)sp;                 // [32][192] raw floats (24KB)
        float* s_sq    = (float*)(sp + 24576);       // [32][24]
        float* s_rowsq = (float*)(sp + 27648);       // [32]

        #pragma unroll
        for (int it = 0; it < 3; it++) {
            int idx = tid + it * 256;                // 0..767
            int r = idx / 24, g = idx % 24;
            int gr = c * 32 + r;
            const float* src = x + (size_t)gr * D + g * 8;
            float4 f0 = *(const float4*)src;
            float4 f1 = *(const float4*)(src + 4);

            half2 hh[4];
            hh[0] = __float22half2_rn(make_float2(f0.x, f0.y));
            hh[1] = __float22half2_rn(make_float2(f0.z, f0.w));
            hh[2] = __float22half2_rn(make_float2(f1.x, f1.y));
            hh[3] = __float22half2_rn(make_float2(f1.z, f1.w));
            *(uint4*)((char*)g_xh + (size_t)gr * 384 +
                      (((uint32_t)g ^ (uint32_t)(gr & 7)) << 4)) = *(uint4*)hh;

            s_sq[r * 24 + g] = f0.x * f0.x + f0.y * f0.y + f0.z * f0.z + f0.w * f0.w
                             + f1.x * f1.x + f1.y * f1.y + f1.z * f1.z + f1.w * f1.w;
            float* sxp = &s_stage[r * D + g * 8];
            sxp[0] = f0.x; sxp[1] = f0.y; sxp[2] = f0.z; sxp[3] = f0.w;
            sxp[4] = f1.x; sxp[5] = f1.y; sxp[6] = f1.z; sxp[7] = f1.w;
        }
        __syncthreads();

        if (tid < 32) {
            float v = 0.f;
            #pragma unroll
            for (int k = 0; k < 24; k++) v += s_sq[tid * 24 + k];
            g_sq[c * 32 + tid] = v;
            s_rowsq[tid] = v;
        }
        if (tid >= 64) {                              // 192 threads -> 192 columns
            int col = tid - 64;
            float cs = 0.f;
            #pragma unroll
            for (int r = 0; r < 32; r++) cs += s_stage[r * D + col];
            atomicAdd(&g_colacc[c & 7][col], cs);     // 8 planes: low contention
        }
        __syncthreads();
        if (tid == 0) {
            float tot = 0.f;
            #pragma unroll
            for (int r = 0; r < 32; r++) tot += s_rowsq[r];
            atomicAdd(&g_sqacc[c & 7], tot);
        }
    }

    // ================= grid barrier + bandwidth constant =================
    __threadfence();
    __syncthreads();
    if (tid == 0) s_go = (atomicAdd(&g_pcount, 1) == NCTA - 1) ? 1 : 0;
    __syncthreads();
    if (s_go) {
        __threadfence();
        float* s_red2 = (float*)sp;
        float cs = 0.f;
        if (tid < D) {
            #pragma unroll
            for (int r = 0; r < 8; r++) cs += __ldcg(&g_colacc[r][tid]);
        }
        s_red2[tid] = cs * cs;
        __syncthreads();
        #pragma unroll
        for (int o = 128; o >= 32; o >>= 1) {
            if (tid < o) s_red2[tid] += s_red2[tid + o];
            __syncthreads();
        }
        if (tid < 32) {
            float v = s_red2[tid];
            #pragma unroll
            for (int o = 16; o > 0; o >>= 1) v += __shfl_down_sync(0xffffffffu, v, o);
            if (tid == 0) {
                float sumsq = 0.f;
                #pragma unroll
                for (int r = 0; r < 8; r++) sumsq += __ldcg(&g_sqacc[r]);
                double sumL2 = 2.0 * (double)N * (double)sumsq - 2.0 * (double)v;
                double bw = sumL2 / ((double)N * (double)N - (double)N);
                bw *= 0.25;                           // / KERNEL_MUL^(KERNEL_NUM//2)
                g_c2 = (float)(1.4426950408889634 / (bw * 16.0));
                g_loss = 0.0;
                __threadfence();
                atomicExch(&g_ready, 1);
            }
        }
    }
    if (tid == 0) {
        volatile int* rp = &g_ready;
        while (*rp == 0) {}
    }
    __syncthreads();
    __threadfence();

    // ================= phase 2: persistent HMMA tile loop =================
    int start = (c < REMW) ? c * (QW + 1) : REMW * (QW + 1) + (c - REMW) * QW;
    int count = (c < REMW) ? QW + 1 : QW;
    int bi = 0, s = start;
    while (s >= NB - bi) { s -= NB - bi; bi++; }
    int bj = bi + s;

    uint32_t mbar = sb + OFF_MBAR;
    if (tid == 0) MBAR_INIT(mbar, 1);
    __syncthreads();
    if (tid == 0) {
        MBAR_EXPECT_TX(mbar, 2 * TILE_BYTES);
        const char* xh = (const char*)g_xh;
        bulk_g2s(sb + OFF_A, xh + (size_t)bi * TILE_BYTES, TILE_BYTES, mbar);
        bulk_g2s(sb + OFF_B, xh + (size_t)bj * TILE_BYTES, TILE_BYTES, mbar);
    }

    // ---- anti-phase stagger: second CTA on each SM (classic placement: bid%148)
    // delays ~half a tile so its MMA phase overlaps the other CTA's epilogue.
    if (c >= 148) {
        if (tid == 0) {
            long long t0 = clock64();
            while (clock64() - t0 < STAGGER) {}
        }
        __syncthreads();
    }

    uint32_t swz   = (uint32_t)(lane & 7);
    uint32_t ahi   = (uint32_t)(lane >> 4);
    uint32_t bhi   = (uint32_t)((lane >> 3) & 1);
    uint32_t baseA = sb + OFF_A + (uint32_t)(wM * 64 + (lane & 15)) * 384u;
    uint32_t baseB = sb + OFF_B + (uint32_t)(wN * 32 + ((lane >> 4) << 3) + (lane & 7)) * 384u;

    float c2 = __ldcg(&g_c2), tc2 = 2.f * c2, nc2 = -c2;

    float A0 = 0.f, A1 = 0.f, dtot = 0.f;
    int phase = 0;

    for (int k = 0; k < count; k++) {
        bool diag = (bi == bj);
        float nsi[8], nsj[8];
        #pragma unroll
        for (int fm = 0; fm < 4; fm++) {
            nsi[fm * 2]     = nc2 * __ldg(&g_sq[bi * BM + wM * 64 + fm * 16 + gID]);
            nsi[fm * 2 + 1] = nc2 * __ldg(&g_sq[bi * BM + wM * 64 + fm * 16 + gID + 8]);
        }
        #pragma unroll
        for (int fn = 0; fn < 4; fn++) {
            nsj[fn * 2]     = nc2 * __ldg(&g_sq[bj * BM + wN * 32 + fn * 8 + tig * 2]);
            nsj[fn * 2 + 1] = nc2 * __ldg(&g_sq[bj * BM + wN * 32 + fn * 8 + tig * 2 + 1]);
        }

        MBAR_WAIT(mbar, phase);
        phase ^= 1;

        uint32_t accH[4][4][2];
        #pragma unroll
        for (int a = 0; a < 4; a++)
            #pragma unroll
            for (int b = 0; b < 4; b++) { accH[a][b][0] = 0u; accH[a][b][1] = 0u; }

        #pragma unroll
        for (int kg = 0; kg < 12; kg++) {
            uint32_t a[4][4], b[2][4];
            uint32_t ga = (uint32_t)(2 * kg) + ahi;
            uint32_t gb = (uint32_t)(2 * kg) + bhi;
            #pragma unroll
            for (int fm = 0; fm < 4; fm++) {
                uint32_t ad = baseA + (uint32_t)fm * 6144u + ((ga ^ swz) << 4);
                LDSM_X4(a[fm][0], a[fm][1], a[fm][2], a[fm][3], ad);
            }
            #pragma unroll
            for (int q = 0; q < 2; q++) {
                uint32_t bd = baseB + (uint32_t)q * 6144u + ((gb ^ swz) << 4);
                LDSM_X4(b[q][0], b[q][1], b[q][2], b[q][3], bd);
            }
            #pragma unroll
            for (int fm = 0; fm < 4; fm++)
                #pragma unroll
                for (int fn = 0; fn < 4; fn++)
                    MMA16816H(accH[fm][fn], a[fm], b[fn >> 1][(fn & 1) * 2], b[fn >> 1][(fn & 1) * 2 + 1]);
        }
        __syncthreads();   // smem reads done -> safe to overwrite tiles

        int nbi = bi, nbj = bj + 1;
        if (nbj == NB) { nbi = bi + 1; nbj = nbi; }
        if (k + 1 < count && tid == 0) {
            uint32_t bytes = TILE_BYTES + ((nbi != bi) ? TILE_BYTES : 0);
            MBAR_EXPECT_TX(mbar, bytes);
            const char* xh = (const char*)g_xh;
            if (nbi != bi)
                bulk_g2s(sb + OFF_A, xh + (size_t)nbi * TILE_BYTES, TILE_BYTES, mbar);
            bulk_g2s(sb + OFF_B, xh + (size_t)nbj * TILE_BYTES, TILE_BYTES, mbar);
        }

        // ------------- fp32 epilogue (dominant err = fp16 dot) -------------
        if (!diag) {
            #pragma unroll
            for (int fm = 0; fm < 4; fm++)
                #pragma unroll
                for (int fn = 0; fn < 4; fn++) {
                    float2 p0 = __half22float2(*(half2*)&accH[fm][fn][0]);
                    float2 p1 = __half22float2(*(half2*)&accH[fm][fn][1]);
                    float n00 = nsi[fm * 2]     + nsj[fn * 2];
                    float n01 = nsi[fm * 2]     + nsj[fn * 2 + 1];
                    float n10 = nsi[fm * 2 + 1] + nsj[fn * 2];
                    float n11 = nsi[fm * 2 + 1] + nsj[fn * 2 + 1];
                    {
                        float t = ex2f(fmaf(p0.x, tc2, n00));
                        float t2 = t * t, t4 = t2 * t2, t8 = t4 * t4;
                        A0 += (fmaf(t, t, t) + fmaf(t4, t4, t4)) + t8 * t8;
                    }
                    {
                        float t = ex2f(fmaf(p0.y, tc2, n01));
                        float t2 = t * t, t4 = t2 * t2, t8 = t4 * t4;
                        A1 += (fmaf(t, t, t) + fmaf(t4, t4, t4)) + t8 * t8;
                    }
                    {
                        float t = ex2f(fmaf(p1.x, tc2, n10));
                        float t2 = t * t, t4 = t2 * t2, t8 = t4 * t4;
                        A0 += (fmaf(t, t, t) + fmaf(t4, t4, t4)) + t8 * t8;
                    }
                    {
                        float t = ex2f(fmaf(p1.y, tc2, n11));
                        float t2 = t * t, t4 = t2 * t2, t8 = t4 * t4;
                        A1 += (fmaf(t, t, t) + fmaf(t4, t4, t4)) + t8 * t8;
                    }
                }
        } else {
            #pragma unroll
            for (int fm = 0; fm < 4; fm++)
                #pragma unroll
                for (int fn = 0; fn < 4; fn++) {
                    float2 p0 = __half22float2(*(half2*)&accH[fm][fn][0]);
                    float2 p1 = __half22float2(*(half2*)&accH[fm][fn][1]);
                    float dots[4] = {p0.x, p0.y, p1.x, p1.y};
                    #pragma unroll
                    for (int r = 0; r < 4; r++) {
                        int gi = bi * BM + wM * 64 + fm * 16 + gID + (r >> 1) * 8;
                        int gj = bj * BM + wN * 32 + fn * 8 + tig * 2 + (r & 1);
                        float arg = fminf(fmaf(dots[r], tc2,
                                               nsi[fm * 2 + (r >> 1)] + nsj[fn * 2 + (r & 1)]), 0.f);
                        float t = ex2f(arg);
                        float t2 = t * t, t4 = t2 * t2, t8 = t4 * t4;
                        float ks = (fmaf(t, t, t) + fmaf(t4, t4, t4)) + t8 * t8;
                        float w = (gj > gi) ? (((gi ^ gj) & 1) ? -2.f : 2.f) : 0.f;
                        dtot = fmaf(w, ks, dtot);
                    }
                }
        }
        bi = nbi; bj = nbj;
    }

    float part = ((gID & 1) ? (A1 - A0) : (A0 - A1)) * 2.f + dtot;
    #pragma unroll
    for (int o = 16; o > 0; o >>= 1) part += __shfl_xor_sync(0xffffffffu, part, o);
    float* s_red = (float*)(sp + OFF_RED);
    if (lane == 0) s_red[wid] = part;
    __syncthreads();
    if (tid == 0) {
        float v = 0.f;
        #pragma unroll
        for (int w = 0; w < 8; w++) v += s_red[w];
        atomicAdd(&g_loss, (double)v);
    }

    // ================= finalization by last CTA (parallel state reset) =================
    __threadfence();
    __syncthreads();
    if (tid == 0) s_win = (atomicAdd(&g_mcount, 1) == NCTA - 1) ? 1 : 0;
    __syncthreads();
    if (s_win) {
        __threadfence();
        if (tid < D) {
            #pragma unroll
            for (int r = 0; r < 8; r++) g_colacc[r][tid] = 0.f;
        }
        if (tid < 8) g_sqacc[tid] = 0.f;
        __syncthreads();
        if (tid == 0) {
            double half = (double)(N / 2);
            out[0] = (float)((g_loss + 5.0 * (double)N) / (half * half));
            g_pcount = 0;
            g_ready  = 0;
            g_mcount = 0;
        }
    }
}

// ---------------- launch ----------------
extern "C" void kernel_launch(void* const* d_in, const int* in_sizes, int n_in,
                              void* d_out, int out_size) {
    const float* x = (const float*)d_in[0];
    float* out = (float*)d_out;

    cudaFuncSetAttribute(k_all, cudaFuncAttributeMaxDynamicSharedMemorySize, SMEM_DYN);
    k_all<<<NCTA, 256, SMEM_DYN>>>(x, out);
}

// round 10
// speedup vs baseline: 1.0351x; 1.0351x over previous
#include <cuda_runtime.h>
#include <cuda_fp16.h>
#include <cstdint>

#define N        8192
#define D        192
#define BM       128
#define NB       64
#define NTILES   2080             // NB*(NB+1)/2
#define TILE_BYTES (BM * D * 2)   // 49152
#define NCTA     296              // 148 SM x 2 (all co-resident: barrier-safe)
#define QW       7                // NTILES / NCTA
#define REMW     8                // NTILES - NCTA*QW
#define CHUNKS   256              // 8192 rows / 32

// ---------------- device globals (zero-initialized at load) ----------------
__device__ double g_loss;
__device__ float  g_colacc[8][D];
__device__ float  g_sqacc[8];
__device__ int    g_pcount;
__device__ int    g_ready;
__device__ int    g_mcount;
__device__ float  g_sq[N];
__device__ float  g_c2;                 // log2(e)/(16*bw)
__device__ uint4  g_xh[N * D * 2 / 16]; // fp16 x, row stride 384B, 16B-group XOR swizzle

// ---------------- helpers ----------------
__device__ __forceinline__ uint32_t smem_u32(const void* p) {
    uint32_t a;
    asm("{ .reg .u64 t; cvta.to.shared.u64 t, %1; cvt.u32.u64 %0, t; }" : "=r"(a) : "l"(p));
    return a;
}
#define MBAR_INIT(a, c) asm volatile("mbarrier.init.shared.b64 [%0], %1;" :: "r"(a), "r"(c) : "memory")
#define MBAR_EXPECT_TX(a, b) asm volatile("mbarrier.arrive.expect_tx.shared.b64 _, [%0], %1;" :: "r"(a), "r"(b) : "memory")
#define MBAR_WAIT(a, ph) do { \
    uint32_t _m = (a), _p = (ph), _d; \
    asm volatile("{ .reg .pred p; mbarrier.try_wait.parity.acquire.cta.shared::cta.b64 p, [%1], %2; selp.b32 %0,1,0,p; }" \
        : "=r"(_d) : "r"(_m), "r"(_p) : "memory"); \
    if (!_d) { asm volatile("{ .reg .pred P1; WL_%=: mbarrier.try_wait.parity.acquire.cta.shared::cta.b64 P1, [%0], %1, 0x989680; @P1 bra.uni WD_%=; bra.uni WL_%=; WD_%=: }" \
        :: "r"(_m), "r"(_p) : "memory"); } } while (0)
__device__ __forceinline__ void bulk_g2s(uint32_t dst, const void* src, uint32_t bytes, uint32_t mbar) {
    asm volatile("cp.async.bulk.shared::cluster.global.mbarrier::complete_tx::bytes [%0], [%1], %2, [%3];"
        :: "r"(dst), "l"(src), "r"(bytes), "r"(mbar) : "memory");
}
#define LDSM_X4(r0, r1, r2, r3, a) \
    asm volatile("ldmatrix.sync.aligned.m8n8.x4.shared.b16 {%0,%1,%2,%3}, [%4];" \
        : "=r"(r0), "=r"(r1), "=r"(r2), "=r"(r3) : "r"(a))
#define MMA16816H(d, a, b0, b1) \
    asm volatile("mma.sync.aligned.m16n8k16.row.col.f16.f16.f16.f16 " \
        "{%0,%1},{%2,%3,%4,%5},{%6,%7},{%0,%1};" \
        : "+r"((d)[0]), "+r"((d)[1]) \
        : "r"((a)[0]), "r"((a)[1]), "r"((a)[2]), "r"((a)[3]), "r"(b0), "r"(b1))
__device__ __forceinline__ float ex2f(float x) {
    float r; asm("ex2.approx.ftz.f32 %0, %1;" : "=f"(r) : "f"(x)); return r;
}

// one k-step for a 32-row half (2 fm sub-blocks): 4 LDSM + 8 MMA
#define KSTEP(ACC, FOFF, KG) do { \
    uint32_t _a0[4], _a1[4], _b0[4], _b1[4]; \
    uint32_t _ga = (((uint32_t)(2*(KG)) + ahi) ^ swz) << 4; \
    uint32_t _gb = (((uint32_t)(2*(KG)) + bhi) ^ swz) << 4; \
    LDSM_X4(_a0[0],_a0[1],_a0[2],_a0[3], baseA + (FOFF) + _ga); \
    LDSM_X4(_a1[0],_a1[1],_a1[2],_a1[3], baseA + (FOFF) + 6144u + _ga); \
    LDSM_X4(_b0[0],_b0[1],_b0[2],_b0[3], baseB + _gb); \
    LDSM_X4(_b1[0],_b1[1],_b1[2],_b1[3], baseB + 6144u + _gb); \
    MMA16816H((ACC)[0][0], _a0, _b0[0], _b0[1]); \
    MMA16816H((ACC)[0][1], _a0, _b0[2], _b0[3]); \
    MMA16816H((ACC)[0][2], _a0, _b1[0], _b1[1]); \
    MMA16816H((ACC)[0][3], _a0, _b1[2], _b1[3]); \
    MMA16816H((ACC)[1][0], _a1, _b0[0], _b0[1]); \
    MMA16816H((ACC)[1][1], _a1, _b0[2], _b0[3]); \
    MMA16816H((ACC)[1][2], _a1, _b1[0], _b1[1]); \
    MMA16816H((ACC)[1][3], _a1, _b1[2], _b1[3]); \
} while(0)

// epilogue of one acc pair (4 elements) into parity buckets ta0/ta1
#define EPI1(LO, HI, NI0, NI1, NJ0, NJ1) do { \
    float2 _p0 = __half22float2(*(half2*)&(LO)); \
    float2 _p1 = __half22float2(*(half2*)&(HI)); \
    float _t, _t2, _t4, _t8; \
    _t = ex2f(fmaf(_p0.x, tc2, (NI0)+(NJ0))); _t2=_t*_t; _t4=_t2*_t2; _t8=_t4*_t4; \
    ta0 += (fmaf(_t,_t,_t) + fmaf(_t4,_t4,_t4)) + _t8*_t8; \
    _t = ex2f(fmaf(_p0.y, tc2, (NI0)+(NJ1))); _t2=_t*_t; _t4=_t2*_t2; _t8=_t4*_t4; \
    ta1 += (fmaf(_t,_t,_t) + fmaf(_t4,_t4,_t4)) + _t8*_t8; \
    _t = ex2f(fmaf(_p1.x, tc2, (NI1)+(NJ0))); _t2=_t*_t; _t4=_t2*_t2; _t8=_t4*_t4; \
    ta0 += (fmaf(_t,_t,_t) + fmaf(_t4,_t4,_t4)) + _t8*_t8; \
    _t = ex2f(fmaf(_p1.y, tc2, (NI1)+(NJ1))); _t2=_t*_t; _t4=_t2*_t2; _t8=_t4*_t4; \
    ta1 += (fmaf(_t,_t,_t) + fmaf(_t4,_t4,_t4)) + _t8*_t8; \
} while(0)

// ---------------- fused persistent kernel ----------------
#define OFF_A    0
#define OFF_B    49152
#define OFF_MBAR 98304
#define OFF_RED  98320
#define SMEM_DYN (98304 + 64 + 1024)

__global__ __launch_bounds__(256, 2) void k_all(const float* __restrict__ x,
                                                float* __restrict__ out) {
    extern __shared__ char dsm[];
    uint32_t sb = (smem_u32(dsm) + 1023u) & ~1023u;
    char* sp = dsm + (sb - smem_u32(dsm));

    int tid  = threadIdx.x;
    int wid  = tid >> 5, lane = tid & 31;
    int wM   = wid >> 2, wN = wid & 3;
    int gID  = lane >> 2, tig = lane & 3;
    int c    = blockIdx.x;

    __shared__ int s_go, s_win;

    // ================= phase 1: convert + reductions (CTAs 0..255) =================
    if (c < CHUNKS) {
        float* s_stage = (float*)sp;
        float* s_sq    = (float*)(sp + 24576);
        float* s_rowsq = (float*)(sp + 27648);

        #pragma unroll
        for (int it = 0; it < 3; it++) {
            int idx = tid + it * 256;
            int r = idx / 24, g = idx % 24;
            int gr = c * 32 + r;
            const float* src = x + (size_t)gr * D + g * 8;
            float4 f0 = *(const float4*)src;
            float4 f1 = *(const float4*)(src + 4);

            half2 hh[4];
            hh[0] = __float22half2_rn(make_float2(f0.x, f0.y));
            hh[1] = __float22half2_rn(make_float2(f0.z, f0.w));
            hh[2] = __float22half2_rn(make_float2(f1.x, f1.y));
            hh[3] = __float22half2_rn(make_float2(f1.z, f1.w));
            *(uint4*)((char*)g_xh + (size_t)gr * 384 +
                      (((uint32_t)g ^ (uint32_t)(gr & 7)) << 4)) = *(uint4*)hh;

            s_sq[r * 24 + g] = f0.x * f0.x + f0.y * f0.y + f0.z * f0.z + f0.w * f0.w
                             + f1.x * f1.x + f1.y * f1.y + f1.z * f1.z + f1.w * f1.w;
            float* sxp = &s_stage[r * D + g * 8];
            sxp[0] = f0.x; sxp[1] = f0.y; sxp[2] = f0.z; sxp[3] = f0.w;
            sxp[4] = f1.x; sxp[5] = f1.y; sxp[6] = f1.z; sxp[7] = f1.w;
        }
        __syncthreads();

        if (tid < 32) {
            float v = 0.f;
            #pragma unroll
            for (int k = 0; k < 24; k++) v += s_sq[tid * 24 + k];
            g_sq[c * 32 + tid] = v;
            s_rowsq[tid] = v;
        }
        if (tid >= 64) {
            int col = tid - 64;
            float cs = 0.f;
            #pragma unroll
            for (int r = 0; r < 32; r++) cs += s_stage[r * D + col];
            atomicAdd(&g_colacc[c & 7][col], cs);
        }
        __syncthreads();
        if (tid == 0) {
            float tot = 0.f;
            #pragma unroll
            for (int r = 0; r < 32; r++) tot += s_rowsq[r];
            atomicAdd(&g_sqacc[c & 7], tot);
        }
    }

    // ================= grid barrier + bandwidth constant =================
    __threadfence();
    __syncthreads();
    if (tid == 0) s_go = (atomicAdd(&g_pcount, 1) == NCTA - 1) ? 1 : 0;
    __syncthreads();
    if (s_go) {
        __threadfence();
        float* s_red2 = (float*)sp;
        float cs = 0.f;
        if (tid < D) {
            #pragma unroll
            for (int r = 0; r < 8; r++) cs += __ldcg(&g_colacc[r][tid]);
        }
        s_red2[tid] = cs * cs;
        __syncthreads();
        #pragma unroll
        for (int o = 128; o >= 32; o >>= 1) {
            if (tid < o) s_red2[tid] += s_red2[tid + o];
            __syncthreads();
        }
        if (tid < 32) {
            float v = s_red2[tid];
            #pragma unroll
            for (int o = 16; o > 0; o >>= 1) v += __shfl_down_sync(0xffffffffu, v, o);
            if (tid == 0) {
                float sumsq = 0.f;
                #pragma unroll
                for (int r = 0; r < 8; r++) sumsq += __ldcg(&g_sqacc[r]);
                double sumL2 = 2.0 * (double)N * (double)sumsq - 2.0 * (double)v;
                double bw = sumL2 / ((double)N * (double)N - (double)N);
                bw *= 0.25;
                g_c2 = (float)(1.4426950408889634 / (bw * 16.0));
                g_loss = 0.0;
                __threadfence();
                atomicExch(&g_ready, 1);
            }
        }
    }
    if (tid == 0) {
        volatile int* rp = &g_ready;
        while (*rp == 0) {}
    }
    __syncthreads();
    __threadfence();

    // ================= phase 2: persistent HMMA tile loop =================
    int start = (c < REMW) ? c * (QW + 1) : REMW * (QW + 1) + (c - REMW) * QW;
    int count = (c < REMW) ? QW + 1 : QW;
    int bi = 0, s = start;
    while (s >= NB - bi) { s -= NB - bi; bi++; }
    int bj = bi + s;

    uint32_t mbar = sb + OFF_MBAR;
    if (tid == 0) MBAR_INIT(mbar, 1);
    __syncthreads();
    if (tid == 0) {
        MBAR_EXPECT_TX(mbar, 2 * TILE_BYTES);
        const char* xh = (const char*)g_xh;
        bulk_g2s(sb + OFF_A, xh + (size_t)bi * TILE_BYTES, TILE_BYTES, mbar);
        bulk_g2s(sb + OFF_B, xh + (size_t)bj * TILE_BYTES, TILE_BYTES, mbar);
    }

    uint32_t swz   = (uint32_t)(lane & 7);
    uint32_t ahi   = (uint32_t)(lane >> 4);
    uint32_t bhi   = (uint32_t)((lane >> 3) & 1);
    uint32_t baseA = sb + OFF_A + (uint32_t)(wM * 64 + (lane & 15)) * 384u;
    uint32_t baseB = sb + OFF_B + (uint32_t)(wN * 32 + ((lane >> 4) << 3) + (lane & 7)) * 384u;

    float c2 = __ldcg(&g_c2), tc2 = 2.f * c2, nc2 = -c2;

    float master = 0.f;
    int phase = 0;

    for (int k = 0; k < count; k++) {
        bool diag = (bi == bj);
        float nsi[8], nsj[8];
        #pragma unroll
        for (int fm = 0; fm < 4; fm++) {
            nsi[fm * 2]     = nc2 * __ldg(&g_sq[bi * BM + wM * 64 + fm * 16 + gID]);
            nsi[fm * 2 + 1] = nc2 * __ldg(&g_sq[bi * BM + wM * 64 + fm * 16 + gID + 8]);
        }
        #pragma unroll
        for (int fn = 0; fn < 4; fn++) {
            nsj[fn * 2]     = nc2 * __ldg(&g_sq[bj * BM + wN * 32 + fn * 8 + tig * 2]);
            nsj[fn * 2 + 1] = nc2 * __ldg(&g_sq[bj * BM + wN * 32 + fn * 8 + tig * 2 + 1]);
        }

        MBAR_WAIT(mbar, phase);
        phase ^= 1;

        float ta0 = 0.f, ta1 = 0.f;
        uint32_t acc0[2][4][2], acc1[2][4][2];
        #pragma unroll
        for (int a = 0; a < 2; a++)
            #pragma unroll
            for (int b = 0; b < 4; b++) {
                acc0[a][b][0] = 0u; acc0[a][b][1] = 0u;
                acc1[a][b][0] = 0u; acc1[a][b][1] = 0u;
            }

        // ---- half 0 (rows 0..31 of warp tile): full k sweep ----
        KSTEP(acc0, 0u, 0);  KSTEP(acc0, 0u, 1);  KSTEP(acc0, 0u, 2);
        KSTEP(acc0, 0u, 3);  KSTEP(acc0, 0u, 4);  KSTEP(acc0, 0u, 5);
        KSTEP(acc0, 0u, 6);  KSTEP(acc0, 0u, 7);  KSTEP(acc0, 0u, 8);
        KSTEP(acc0, 0u, 9);  KSTEP(acc0, 0u, 10); KSTEP(acc0, 0u, 11);

        // ---- half 1 MMA with half-0 epilogue interleaved (independent ops) ----
        KSTEP(acc1, 12288u, 0);  KSTEP(acc1, 12288u, 1);  KSTEP(acc1, 12288u, 2);
        EPI1(acc0[0][0][0], acc0[0][0][1], nsi[0], nsi[1], nsj[0], nsj[1]);
        EPI1(acc0[0][1][0], acc0[0][1][1], nsi[0], nsi[1], nsj[2], nsj[3]);
        KSTEP(acc1, 12288u, 3);  KSTEP(acc1, 12288u, 4);  KSTEP(acc1, 12288u, 5);
        EPI1(acc0[0][2][0], acc0[0][2][1], nsi[0], nsi[1], nsj[4], nsj[5]);
        EPI1(acc0[0][3][0], acc0[0][3][1], nsi[0], nsi[1], nsj[6], nsj[7]);
        KSTEP(acc1, 12288u, 6);  KSTEP(acc1, 12288u, 7);  KSTEP(acc1, 12288u, 8);
        EPI1(acc0[1][0][0], acc0[1][0][1], nsi[2], nsi[3], nsj[0], nsj[1]);
        EPI1(acc0[1][1][0], acc0[1][1][1], nsi[2], nsi[3], nsj[2], nsj[3]);
        KSTEP(acc1, 12288u, 9);  KSTEP(acc1, 12288u, 10); KSTEP(acc1, 12288u, 11);
        EPI1(acc0[1][2][0], acc0[1][2][1], nsi[2], nsi[3], nsj[4], nsj[5]);
        EPI1(acc0[1][3][0], acc0[1][3][1], nsi[2], nsi[3], nsj[6], nsj[7]);

        __syncthreads();   // all smem reads done -> safe to overwrite tiles

        int nbi = bi, nbj = bj + 1;
        if (nbj == NB) { nbi = bi + 1; nbj = nbi; }
        if (k + 1 < count && tid == 0) {
            uint32_t bytes = TILE_BYTES + ((nbi != bi) ? TILE_BYTES : 0);
            MBAR_EXPECT_TX(mbar, bytes);
            const char* xh = (const char*)g_xh;
            if (nbi != bi)
                bulk_g2s(sb + OFF_A, xh + (size_t)nbi * TILE_BYTES, TILE_BYTES, mbar);
            bulk_g2s(sb + OFF_B, xh + (size_t)nbj * TILE_BYTES, TILE_BYTES, mbar);
        }

        // ---- half 1 epilogue (overlaps prefetch TMA) ----
        EPI1(acc1[0][0][0], acc1[0][0][1], nsi[4], nsi[5], nsj[0], nsj[1]);
        EPI1(acc1[0][1][0], acc1[0][1][1], nsi[4], nsi[5], nsj[2], nsj[3]);
        EPI1(acc1[0][2][0], acc1[0][2][1], nsi[4], nsi[5], nsj[4], nsj[5]);
        EPI1(acc1[0][3][0], acc1[0][3][1], nsi[4], nsi[5], nsj[6], nsj[7]);
        EPI1(acc1[1][0][0], acc1[1][0][1], nsi[6], nsi[7], nsj[0], nsj[1]);
        EPI1(acc1[1][1][0], acc1[1][1][1], nsi[6], nsi[7], nsj[2], nsj[3]);
        EPI1(acc1[1][2][0], acc1[1][2][1], nsi[6], nsi[7], nsj[4], nsj[5]);
        EPI1(acc1[1][3][0], acc1[1][3][1], nsi[6], nsi[7], nsj[6], nsj[7]);

        // per-tile fold: diag tiles self-count both orderings (+their own diagonal,
        // which replaces the analytic +5N), so weight 1; off-diag tiles weight 2.
        float tp = (gID & 1) ? (ta1 - ta0) : (ta0 - ta1);
        master += diag ? tp : 2.f * tp;

        bi = nbi; bj = nbj;
    }

    float part = master;
    #pragma unroll
    for (int o = 16; o > 0; o >>= 1) part += __shfl_xor_sync(0xffffffffu, part, o);
    float* s_red = (float*)(sp + OFF_RED);
    if (lane == 0) s_red[wid] = part;
    __syncthreads();
    if (tid == 0) {
        float v = 0.f;
        #pragma unroll
        for (int w = 0; w < 8; w++) v += s_red[w];
        atomicAdd(&g_loss, (double)v);
    }

    // ================= finalization by last CTA (parallel state reset) =================
    __threadfence();
    __syncthreads();
    if (tid == 0) s_win = (atomicAdd(&g_mcount, 1) == NCTA - 1) ? 1 : 0;
    __syncthreads();
    if (s_win) {
        __threadfence();
        if (tid < D) {
            #pragma unroll
            for (int r = 0; r < 8; r++) g_colacc[r][tid] = 0.f;
        }
        if (tid < 8) g_sqacc[tid] = 0.f;
        __syncthreads();
        if (tid == 0) {
            double hn = (double)(N / 2);
            out[0] = (float)(g_loss / (hn * hn));   // diag tiles already include ~5N
            g_pcount = 0;
            g_ready  = 0;
            g_mcount = 0;
        }
    }
}

// ---------------- launch ----------------
extern "C" void kernel_launch(void* const* d_in, const int* in_sizes, int n_in,
                              void* d_out, int out_size) {
    const float* x = (const float*)d_in[0];
    float* out = (float*)d_out;

    cudaFuncSetAttribute(k_all, cudaFuncAttributeMaxDynamicSharedMemorySize, SMEM_DYN);
    k_all<<<NCTA, 256, SMEM_DYN>>>(x, out);
}